// round 8
// baseline (speedup 1.0000x reference)
#include <cuda_runtime.h>
#include <math.h>

#define HH 1024
#define WW 1024
#define CC 128
#define NW 16                 // warps per block = columns per block (incl. 2 halo)
#define TPB (NW * 32)
#define COUT (NW - 2)         // 14 output columns per block
#define ROWG 128              // rows per block
#define BATCH 32              // rows per deferred dot-reduce burst

#define VS_FLOATS (2 * 2 * NW * CC)        // 8192  (parity, rowpair, warp, ch)
#define DP_FLOATS (NW * BATCH * 33)        // 16896 (warp, rowslot, lane+pad)
#define SMEM_FLOATS (VS_FLOATS + DP_FLOATS)

// reduce TWO independent values across the warp in one shared butterfly (6 SHFL)
__device__ __forceinline__ float2 redux2(float a, float b, int lane) {
    const unsigned full = 0xffffffffu;
    float z = (lane < 16) ? a : b;
    float w = (lane < 16) ? b : a;
    w = __shfl_xor_sync(full, w, 16);
    z += w;
    #pragma unroll
    for (int o = 8; o > 0; o >>= 1)
        z += __shfl_xor_sync(full, z, o);
    float t = __shfl_xor_sync(full, z, 16);
    float sa = (lane < 16) ? z : t;
    float sb = (lane < 16) ? t : z;
    return make_float2(sa, sb);
}

__device__ __forceinline__ float dot4(float4 v) {
    return v.x * v.x + v.y * v.y + v.z * v.z + v.w * v.w;
}

__global__ void __launch_bounds__(TPB, 2)
cos_sim_stream(const float* __restrict__ in, float* __restrict__ out)
{
    extern __shared__ float smem[];
    float* vsb = smem;                 // vertical-sum exchange ring
    float* dp  = smem + VS_FLOATS;     // per-warp deferred dot partials

    const int lane = threadIdx.x & 31;
    const int wid  = threadIdx.x >> 5;
    const int col  = blockIdx.x * COUT + wid - 1;     // wid 0 / NW-1 = halo
    const bool colok = ((unsigned)col < (unsigned)WW);
    const bool inner = (wid >= 1) && (wid <= COUT);
    const bool outok = colok && inner;
    const int r0 = blockIdx.y * ROWG;

    float* dprow = dp + wid * (BATCH * 33);

    // hoisted exchange pointers (constant per thread, per parity)
    float4*       st0[2]; float4*       st1[2];
    const float4 *l0p[2], *r0p[2], *l1p[2], *r1p[2];
    {
        const int wl = (wid == 0) ? 0 : wid - 1;      // clamp: halo warp never reads
        const int wr = (wid == NW - 1) ? NW - 1 : wid + 1;
        #pragma unroll
        for (int p = 0; p < 2; p++) {
            st0[p] = (float4*)(vsb + ((p * 2 + 0) * NW + wid) * CC + lane * 4);
            st1[p] = (float4*)(vsb + ((p * 2 + 1) * NW + wid) * CC + lane * 4);
            l0p[p] = (const float4*)(vsb + ((p * 2 + 0) * NW + wl) * CC + lane * 4);
            r0p[p] = (const float4*)(vsb + ((p * 2 + 0) * NW + wr) * CC + lane * 4);
            l1p[p] = (const float4*)(vsb + ((p * 2 + 1) * NW + wl) * CC + lane * 4);
            r1p[p] = (const float4*)(vsb + ((p * 2 + 1) * NW + wr) * CC + lane * 4);
        }
    }

    const float* gcol = in + (size_t)col * CC + lane * 4;
    const size_t rowstep = (size_t)WW * CC;
    auto ld = [&](int h) -> float4 {
        float4 v = make_float4(0.f, 0.f, 0.f, 0.f);
        if (colok && (unsigned)h < (unsigned)HH)
            v = *reinterpret_cast<const float4*>(gcol + (size_t)h * rowstep);
        return v;
    };

    // ---- preamble: rows r0-1..r0+2 normalized; raw rows r0+3..r0+6 staged ----
    float4 rA = ld(r0 - 1), rB = ld(r0), rC = ld(r0 + 1), rD = ld(r0 + 2);
    float4 stg[2][2];
    stg[0][0] = ld(r0 + 3);  stg[0][1] = ld(r0 + 4);
    stg[1][0] = ld(r0 + 5);  stg[1][1] = ld(r0 + 6);

    float4 xnA, xnB, xnC, xnD;
    {
        float2 ss = redux2(dot4(rA), dot4(rB), lane);
        const float ia = (ss.x >= 1e-16f) ? rsqrtf(ss.x) : 1e8f;
        const float ib = (ss.y >= 1e-16f) ? rsqrtf(ss.y) : 1e8f;
        xnA = make_float4(rA.x * ia, rA.y * ia, rA.z * ia, rA.w * ia);
        xnB = make_float4(rB.x * ib, rB.y * ib, rB.z * ib, rB.w * ib);
    }
    {
        float2 ss = redux2(dot4(rC), dot4(rD), lane);
        const float ic = (ss.x >= 1e-16f) ? rsqrtf(ss.x) : 1e8f;
        const float id = (ss.y >= 1e-16f) ? rsqrtf(ss.y) : 1e8f;
        xnC = make_float4(rC.x * ic, rC.y * ic, rC.z * ic, rC.w * ic);
        xnD = make_float4(rD.x * id, rD.y * id, rD.z * id, rD.w * id);
    }

    #pragma unroll 2
    for (int k = 0; k < ROWG / 2; k++) {
        const int i = 2 * k;
        const int h = r0 + i;
        const int p = k & 1;

        // normalize rows h+3,h+4 NOW (consumed next iteration) — this chain
        // overlaps the barrier/exchange/dot work below
        float4 s0 = stg[p][0], s1 = stg[p][1];
        float2 ss = redux2(dot4(s0), dot4(s1), lane);
        const float i0 = (ss.x >= 1e-16f) ? rsqrtf(ss.x) : 1e8f;
        const float i1 = (ss.y >= 1e-16f) ? rsqrtf(ss.y) : 1e8f;
        const float4 xnE = make_float4(s0.x * i0, s0.y * i0, s0.z * i0, s0.w * i0);
        const float4 xnF = make_float4(s1.x * i1, s1.y * i1, s1.z * i1, s1.w * i1);
        stg[p][0] = ld(h + 7);                 // refill, 6 rows ahead of consumption
        stg[p][1] = ld(h + 8);

        float4 v0, v1;                         // vertical 3-sums for rows h, h+1
        v0.x = xnA.x + xnB.x + xnC.x;  v0.y = xnA.y + xnB.y + xnC.y;
        v0.z = xnA.z + xnB.z + xnC.z;  v0.w = xnA.w + xnB.w + xnC.w;
        v1.x = xnB.x + xnC.x + xnD.x;  v1.y = xnB.y + xnC.y + xnD.y;
        v1.z = xnB.z + xnC.z + xnD.z;  v1.w = xnB.w + xnC.w + xnD.w;
        *st0[p] = v0;
        *st1[p] = v1;
        __syncthreads();                       // one barrier per 2 rows

        if (inner) {                           // warp-uniform
            const float4 l0 = *l0p[p], q0 = *r0p[p];
            const float4 l1 = *l1p[p], q1 = *r1p[p];

            float d0 =       xnB.x * (l0.x + v0.x + q0.x);
            d0 = fmaf(xnB.y, (l0.y + v0.y + q0.y), d0);
            d0 = fmaf(xnB.z, (l0.z + v0.z + q0.z), d0);
            d0 = fmaf(xnB.w, (l0.w + v0.w + q0.w), d0);
            float d1 =       xnC.x * (l1.x + v1.x + q1.x);
            d1 = fmaf(xnC.y, (l1.y + v1.y + q1.y), d1);
            d1 = fmaf(xnC.z, (l1.z + v1.z + q1.z), d1);
            d1 = fmaf(xnC.w, (l1.w + v1.w + q1.w), d1);

            dprow[(i & 31) * 33 + lane]       = d0;   // defer lane-reduction
            dprow[((i + 1) & 31) * 33 + lane] = d1;

            if ((i & 31) == 30) {              // batch of 32 rows complete
                __syncwarp();
                if (outok) {
                    float s = 0.f;
                    #pragma unroll
                    for (int j = 0; j < 32; j++) s += dprow[lane * 33 + j];
                    out[(size_t)(h - 30 + lane) * WW + col] = s - 1.0f;
                }
                __syncwarp();
            }
        }
        xnA = xnC;  xnB = xnD;  xnC = xnE;  xnD = xnF;
    }
}

extern "C" void kernel_launch(void* const* d_in, const int* in_sizes, int n_in,
                              void* d_out, int out_size)
{
    const float* in = (const float*)d_in[0];
    float* out = (float*)d_out;

    const size_t smem_bytes = SMEM_FLOATS * sizeof(float);   // ~98 KB
    cudaFuncSetAttribute(cos_sim_stream,
                         cudaFuncAttributeMaxDynamicSharedMemorySize,
                         (int)smem_bytes);

    dim3 grid((WW + COUT - 1) / COUT, HH / ROWG);   // 74 x 8
    cos_sim_stream<<<grid, TPB, smem_bytes>>>(in, out);
}

// round 9
// speedup vs baseline: 1.2753x; 1.2753x over previous
#include <cuda_runtime.h>
#include <math.h>
#include <cstdint>

#define HH 1024
#define WW 1024
#define CC 128
#define NW 16                 // warps per block = columns per block (incl. 2 halo)
#define TPB (NW * 32)
#define COUT (NW - 2)         // 14 output columns per block
#define ROWG 128              // rows per block
#define BATCH 32              // rows per deferred dot-reduce burst

#define VS_FLOATS (2 * 2 * NW * CC)        // 8192  (pair, rowparity, warp, ch)
#define DP_FLOATS (NW * BATCH * 33)        // 16896 (warp, rowslot, lane+pad)
#define SMEM_FLOATS (VS_FLOATS + DP_FLOATS)

// ---- packed f32x2 primitives (sm_103a; PTX-only, ptxas won't auto-fuse) ----
__device__ __forceinline__ uint64_t f2mul(uint64_t a, uint64_t b) {
    uint64_t r; asm("mul.rn.f32x2 %0,%1,%2;" : "=l"(r) : "l"(a), "l"(b)); return r;
}
__device__ __forceinline__ uint64_t f2add(uint64_t a, uint64_t b) {
    uint64_t r; asm("add.rn.f32x2 %0,%1,%2;" : "=l"(r) : "l"(a), "l"(b)); return r;
}
__device__ __forceinline__ uint64_t f2fma(uint64_t a, uint64_t b, uint64_t c) {
    uint64_t r; asm("fma.rn.f32x2 %0,%1,%2,%3;" : "=l"(r) : "l"(a), "l"(b), "l"(c)); return r;
}
__device__ __forceinline__ uint64_t pack2(float x, float y) {
    uint64_t r; asm("mov.b64 %0,{%1,%2};" : "=l"(r) : "f"(x), "f"(y)); return r;
}
__device__ __forceinline__ float hsum2(uint64_t v) {
    float x, y; asm("mov.b64 {%0,%1},%2;" : "=f"(x), "=f"(y) : "l"(v)); return x + y;
}

// sum of squares of a packed 4-vector (2x f32x2)
__device__ __forceinline__ float dot4p(ulonglong2 v) {
    return hsum2(f2fma(v.y, v.y, f2mul(v.x, v.x)));
}

// reduce TWO independent values across the warp in one shared butterfly (6 SHFL)
__device__ __forceinline__ float2 redux2(float a, float b, int lane) {
    const unsigned full = 0xffffffffu;
    float z = (lane < 16) ? a : b;
    float w = (lane < 16) ? b : a;
    w = __shfl_xor_sync(full, w, 16);
    z += w;
    #pragma unroll
    for (int o = 8; o > 0; o >>= 1)
        z += __shfl_xor_sync(full, z, o);
    float t = __shfl_xor_sync(full, z, 16);
    float sa = (lane < 16) ? z : t;
    float sb = (lane < 16) ? t : z;
    return make_float2(sa, sb);
}

__global__ void __launch_bounds__(TPB, 2)
cos_sim_stream(const float* __restrict__ in, float* __restrict__ out)
{
    extern __shared__ float smem[];
    float* vsb = smem;                 // vertical-sum exchange ring
    float* dp  = smem + VS_FLOATS;     // per-warp deferred dot partials

    const int lane = threadIdx.x & 31;
    const int wid  = threadIdx.x >> 5;
    const int col  = blockIdx.x * COUT + wid - 1;     // wid 0 / NW-1 = halo
    const bool colok = ((unsigned)col < (unsigned)WW);
    const bool inner = (wid >= 1) && (wid <= COUT);
    const bool outok = colok && inner;
    const int r0 = blockIdx.y * ROWG;

    float* dprow = dp + wid * (BATCH * 33);
    auto vsp = [&](int pair, int rp, int w) {
        return vsb + ((pair * 2 + rp) * NW + w) * CC;
    };

    const float* gcol = in + (size_t)col * CC + lane * 4;
    const size_t rowstep = (size_t)WW * CC;
    auto ld = [&](int h) -> ulonglong2 {
        ulonglong2 v; v.x = 0ull; v.y = 0ull;
        if (colok && (unsigned)h < (unsigned)HH)
            v = *reinterpret_cast<const ulonglong2*>(gcol + (size_t)h * rowstep);
        return v;
    };
    auto scalev = [&](ulonglong2 v, float inv) -> ulonglong2 {
        const uint64_t ip = pack2(inv, inv);
        ulonglong2 r; r.x = f2mul(v.x, ip); r.y = f2mul(v.y, ip); return r;
    };

    // ---- preamble: normalize rows r0-1, r0 (paired reduce); 4 rows staged ----
    ulonglong2 xnA, xnB;
    {
        ulonglong2 ra = ld(r0 - 1), rb = ld(r0);
        float2 ss = redux2(dot4p(ra), dot4p(rb), lane);
        xnA = scalev(ra, (ss.x >= 1e-16f) ? rsqrtf(ss.x) : 1e8f);
        xnB = scalev(rb, (ss.y >= 1e-16f) ? rsqrtf(ss.y) : 1e8f);
    }
    ulonglong2 stg[2][2];
    stg[0][0] = ld(r0 + 1);  stg[0][1] = ld(r0 + 2);
    stg[1][0] = ld(r0 + 3);  stg[1][1] = ld(r0 + 4);

    #pragma unroll 2
    for (int k = 0; k < ROWG / 2; k++) {
        const int i = 2 * k;
        const int h = r0 + i;
        const int p = k & 1;

        // normalize rows h+1, h+2 with ONE paired butterfly
        ulonglong2 s0 = stg[p][0], s1 = stg[p][1];
        float2 ss = redux2(dot4p(s0), dot4p(s1), lane);
        const ulonglong2 xnC = scalev(s0, (ss.x >= 1e-16f) ? rsqrtf(ss.x) : 1e8f);
        const ulonglong2 xnD = scalev(s1, (ss.y >= 1e-16f) ? rsqrtf(ss.y) : 1e8f);
        stg[p][0] = ld(h + 5);                 // refill, 4 rows ahead
        stg[p][1] = ld(h + 6);

        ulonglong2 v0, v1;                     // vertical 3-sums (packed)
        v0.x = f2add(f2add(xnA.x, xnB.x), xnC.x);
        v0.y = f2add(f2add(xnA.y, xnB.y), xnC.y);
        v1.x = f2add(f2add(xnB.x, xnC.x), xnD.x);
        v1.y = f2add(f2add(xnB.y, xnC.y), xnD.y);
        *reinterpret_cast<ulonglong2*>(vsp(p, 0, wid) + lane * 4) = v0;
        *reinterpret_cast<ulonglong2*>(vsp(p, 1, wid) + lane * 4) = v1;
        __syncthreads();                       // one barrier per 2 rows

        if (inner) {                           // warp-uniform
            const ulonglong2 l0 = *reinterpret_cast<const ulonglong2*>(vsp(p, 0, wid - 1) + lane * 4);
            const ulonglong2 q0 = *reinterpret_cast<const ulonglong2*>(vsp(p, 0, wid + 1) + lane * 4);
            const ulonglong2 l1 = *reinterpret_cast<const ulonglong2*>(vsp(p, 1, wid - 1) + lane * 4);
            const ulonglong2 q1 = *reinterpret_cast<const ulonglong2*>(vsp(p, 1, wid + 1) + lane * 4);

            // d = xn(h) . (left + own + right) per packed half, then horizontal
            uint64_t t0 = f2mul(xnB.x, f2add(f2add(l0.x, v0.x), q0.x));
            t0 = f2fma(xnB.y, f2add(f2add(l0.y, v0.y), q0.y), t0);
            uint64_t t1 = f2mul(xnC.x, f2add(f2add(l1.x, v1.x), q1.x));
            t1 = f2fma(xnC.y, f2add(f2add(l1.y, v1.y), q1.y), t1);
            const float d0 = hsum2(t0);
            const float d1 = hsum2(t1);

            dprow[(i & 31) * 33 + lane]       = d0;   // defer the lane-reduction
            dprow[((i + 1) & 31) * 33 + lane] = d1;

            if ((i & 31) == 30) {              // batch of 32 rows complete
                __syncwarp();
                if (outok) {
                    float s = 0.f;
                    #pragma unroll
                    for (int j = 0; j < 32; j++) s += dprow[lane * 33 + j];
                    out[(size_t)(h - 30 + lane) * WW + col] = s - 1.0f;
                }
                __syncwarp();
            }
        }
        xnA = xnC;  xnB = xnD;
    }
}

extern "C" void kernel_launch(void* const* d_in, const int* in_sizes, int n_in,
                              void* d_out, int out_size)
{
    const float* in = (const float*)d_in[0];
    float* out = (float*)d_out;

    const size_t smem_bytes = SMEM_FLOATS * sizeof(float);   // ~98 KB
    cudaFuncSetAttribute(cos_sim_stream,
                         cudaFuncAttributeMaxDynamicSharedMemorySize,
                         (int)smem_bytes);

    dim3 grid((WW + COUT - 1) / COUT, HH / ROWG);   // 74 x 8
    cos_sim_stream<<<grid, TPB, smem_bytes>>>(in, out);
}